// round 6
// baseline (speedup 1.0000x reference)
#include <cuda_runtime.h>
#include <math.h>

// Problem constants (fixed by the reference)
#define BB 4
#define CC 128
#define HH 240
#define WW 320
#define NN 1024
#define NPTS (BB * NN)          // 4096 points
#define EPSV 1e-9f
#define HWSZ (HH * WW)          // 76800
#define PTS_PER_BLOCK 2
#define NBLOCKS (NPTS / PTS_PER_BLOCK)   // 2048

// Per-block partials: every slot overwritten each launch -> no init needed.
__device__ double g_pe1[NBLOCKS];
__device__ double g_pld[NBLOCKS];

// Block: 256 threads, 2 points. Phase 1 stages each point's gather footprint
// (128ch x 16 F_b values + 128ch x 4 F_a values) into SMEM with consecutive
// lanes on consecutive addresses within a channel (coalesced -> ~8-10 L1tex
// wavefronts per warp-LDG instead of 32). Phase 2: thread = (point, channel);
// identical per-channel math from conflict-free SMEM; 9-sum reduction;
// per-point 2x2 GN epilogue; per-block partial write.
__global__ __launch_bounds__(256) void gn_main_kernel(
    const float* __restrict__ Fa,
    const float* __restrict__ Fb,
    const float* __restrict__ ma,
    const float* __restrict__ mb,
    const float* __restrict__ nz)
{
    __shared__ float st_fb[PTS_PER_BLOCK][CC * 17];   // 16 vals/ch, pad 17
    __shared__ float st_fa[PTS_PER_BLOCK][CC * 5];    // 4 vals/ch, pad 5
    __shared__ int   sh_cxs[PTS_PER_BLOCK][4];
    __shared__ int   sh_roff[PTS_PER_BLOCK][4];
    __shared__ int   sh_aoff[PTS_PER_BLOCK][4];
    __shared__ float s9[8][12];
    __shared__ double sh_e1[PTS_PER_BLOCK];
    __shared__ double sh_ld[PTS_PER_BLOCK];

    const int tid  = threadIdx.x;
    const int lp   = tid >> 7;          // local point 0/1
    const int t    = tid & 127;         // thread within point
    const int lane = tid & 31;
    const int w    = tid >> 5;          // warp 0..7 (w<4: point0, w>=4: point1)
    const int pi   = blockIdx.x * PTS_PER_BLOCK + lp;
    const int b    = pi >> 10;

    // ---- per-point coordinate setup (uniform per point) ----
    const float xa  = ma[pi * 2 + 0] * 0.125f;
    const float ya  = ma[pi * 2 + 1] * 0.125f;
    const float ubx = mb[pi * 2 + 0] * 0.125f;
    const float uby = mb[pi * 2 + 1] * 0.125f;
    const float xsx = 2.0f * nz[pi * 2 + 0] - 1.0f + ubx;
    const float xsy = 2.0f * nz[pi * 2 + 1] - 1.0f + uby;

    // F_a bilinear
    const float fax0 = floorf(xa), fay0 = floorf(ya);
    const float wxa = xa - fax0, wya = ya - fay0;
    int ax0 = min(max((int)fax0, 0), WW - 1);
    int ax1 = min(ax0 + 1, WW - 1);
    int ay0 = min(max((int)fay0, 0), HH - 1);
    int ay1 = min(ay0 + 1, HH - 1);

    // F_b bilinear + gradient footprint
    const float fbx0 = floorf(xsx), fby0 = floorf(xsy);
    const float wxb = xsx - fbx0, wyb = xsy - fby0;
    int bx0 = min(max((int)fbx0, 0), WW - 1);
    int bx1 = min(bx0 + 1, WW - 1);
    int by0 = min(max((int)fby0, 0), HH - 1);
    int by1 = min(by0 + 1, HH - 1);
    const int cxs0 = max(bx0 - 1, 0);
    const int cxs3 = min(bx1 + 1, WW - 1);
    const int rys0 = max(by0 - 1, 0);
    const int rys3 = min(by1 + 1, HH - 1);
    const int sx = (bx1 > bx0) ? 1 : 0;
    const int sy = (by1 > by0) ? 1 : 0;

    if (t == 0) {
        sh_cxs[lp][0] = cxs0;  sh_cxs[lp][1] = bx0;
        sh_cxs[lp][2] = bx1;   sh_cxs[lp][3] = cxs3;
        sh_roff[lp][0] = rys0 * WW;  sh_roff[lp][1] = by0 * WW;
        sh_roff[lp][2] = by1 * WW;   sh_roff[lp][3] = rys3 * WW;
        sh_aoff[lp][0] = ay0 * WW + ax0;  sh_aoff[lp][1] = ay0 * WW + ax1;
        sh_aoff[lp][2] = ay1 * WW + ax0;  sh_aoff[lp][3] = ay1 * WW + ax1;
    }
    __syncthreads();

    const float* __restrict__ FaB = Fa + (size_t)b * CC * HWSZ;
    const float* __restrict__ FbB = Fb + (size_t)b * CC * HWSZ;

    // ---- phase 1: coalesced staging ----
    // F_b: 2048 values, value idx v = i*128 + t -> (c = v>>4, m = v&15)
    #pragma unroll
    for (int i = 0; i < 16; i++) {
        const int v = i * 128 + t;
        const int c = v >> 4;
        const int m = v & 15;
        const int addr = c * HWSZ + sh_roff[lp][m >> 2] + sh_cxs[lp][m & 3];
        st_fb[lp][c * 17 + m] = __ldg(FbB + addr);
    }
    // F_a: 512 values, u = i*128 + t -> (c = u>>2, j = u&3)
    #pragma unroll
    for (int i = 0; i < 4; i++) {
        const int u = i * 128 + t;
        const int c = u >> 2;
        const int j = u & 3;
        st_fa[lp][c * 5 + j] = __ldg(FaB + c * HWSZ + sh_aoff[lp][j]);
    }
    __syncthreads();

    // ---- phase 2: per-channel math (thread = channel) ----
    const float wb00 = (1.f - wxb) * (1.f - wyb);
    const float wb01 = wxb * (1.f - wyb);
    const float wb10 = (1.f - wxb) * wyb;
    const float wb11 = wxb * wyb;
    const float wa00 = (1.f - wxa) * (1.f - wya);
    const float wa01 = wxa * (1.f - wya);
    const float wa10 = (1.f - wxa) * wya;
    const float wa11 = wxa * wya;

    float vv[4][4];
    {
        const float* p = &st_fb[lp][t * 17];
        #pragma unroll
        for (int r = 0; r < 4; r++)
            #pragma unroll
            for (int k = 0; k < 4; k++)
                vv[r][k] = p[r * 4 + k];
    }
    const float* pa = &st_fa[lp][t * 5];
    const float a00 = pa[0], a01 = pa[1], a10 = pa[2], a11 = pa[3];

    const float fs = wb00 * vv[1][1] + wb01 * vv[1][2] + wb10 * vv[2][1] + wb11 * vv[2][2];
    const float Jx = 0.5f * (wb00 * (vv[1][2] - vv[1][0]) + wb01 * (vv[1][3] - vv[1][sx]) +
                             wb10 * (vv[2][2] - vv[2][0]) + wb11 * (vv[2][3] - vv[2][sx]));
    const float Jy = 0.5f * (wb00 * (vv[2][1] - vv[0][1]) + wb01 * (vv[2][2] - vv[0][2]) +
                             wb10 * (vv[3][1] - vv[sy][1]) + wb11 * (vv[3][2] - vv[sy][2]));
    const float ft = wa00 * a00 + wa01 * a01 + wa10 * a10 + wa11 * a11;

    float s_tt = ft * ft, s_ss = fs * fs;
    float s_xs = Jx * fs, s_xt = Jx * ft;
    float s_ys = Jy * fs, s_yt = Jy * ft;
    float s_xx = Jx * Jx, s_xy = Jx * Jy, s_yy = Jy * Jy;

    // warp reduction (32 lanes = 32 channels)
    #pragma unroll
    for (int o = 16; o > 0; o >>= 1) {
        s_tt += __shfl_xor_sync(0xFFFFFFFFu, s_tt, o);
        s_ss += __shfl_xor_sync(0xFFFFFFFFu, s_ss, o);
        s_xs += __shfl_xor_sync(0xFFFFFFFFu, s_xs, o);
        s_xt += __shfl_xor_sync(0xFFFFFFFFu, s_xt, o);
        s_ys += __shfl_xor_sync(0xFFFFFFFFu, s_ys, o);
        s_yt += __shfl_xor_sync(0xFFFFFFFFu, s_yt, o);
        s_xx += __shfl_xor_sync(0xFFFFFFFFu, s_xx, o);
        s_xy += __shfl_xor_sync(0xFFFFFFFFu, s_xy, o);
        s_yy += __shfl_xor_sync(0xFFFFFFFFu, s_yy, o);
    }
    if (lane == 0) {
        s9[w][0] = s_tt; s9[w][1] = s_ss; s9[w][2] = s_xs; s9[w][3] = s_xt;
        s9[w][4] = s_ys; s9[w][5] = s_yt; s9[w][6] = s_xx; s9[w][7] = s_xy;
        s9[w][8] = s_yy;
    }
    __syncthreads();

    // ---- per-point epilogue (one thread per point) ----
    if (t == 0) {
        const int wb = lp * 4;
        float r9[9];
        #pragma unroll
        for (int j = 0; j < 9; j++)
            r9[j] = s9[wb][j] + s9[wb + 1][j] + s9[wb + 2][j] + s9[wb + 3][j];

        const float invnt = 1.f / fmaxf(sqrtf(r9[0]), 1e-12f);
        const float invns = 1.f / fmaxf(sqrtf(r9[1]), 1e-12f);
        const float bxv = r9[2] * invns - r9[3] * invnt;
        const float byv = r9[4] * invns - r9[5] * invnt;
        const float aH = r9[6] + EPSV;
        const float dH = r9[8] + EPSV;
        const float bH = r9[7];
        const float det = aH * dH - bH * bH;
        const float inv_det = 1.f / det;
        const float ddx = (dH * bxv - bH * byv) * inv_det;
        const float ddy = (aH * byv - bH * bxv) * inv_det;
        const float dx = (ubx - xsx) + ddx;
        const float dy = (uby - xsy) + ddy;
        sh_e1[lp] = 0.5 * (double)(aH * dx * dx + 2.f * bH * dx * dy + dH * dy * dy);
        sh_ld[lp] = log((double)det);
    }
    __syncthreads();

    if (tid == 0) {
        g_pe1[blockIdx.x] = sh_e1[0] + sh_e1[1];
        g_pld[blockIdx.x] = sh_ld[0] + sh_ld[1];
    }
}

__global__ __launch_bounds__(256) void gn_finalize_kernel(float* __restrict__ out) {
    const int t = threadIdx.x;
    double e1 = 0.0, ld = 0.0;
    #pragma unroll
    for (int i = 0; i < NBLOCKS / 256; i++) {
        e1 += g_pe1[t + i * 256];
        ld += g_pld[t + i * 256];
    }
    __shared__ double se1[256];
    __shared__ double sld[256];
    se1[t] = e1; sld[t] = ld;
    __syncthreads();
    #pragma unroll
    for (int s = 128; s > 0; s >>= 1) {
        if (t < s) { se1[t] += se1[t + s]; sld[t] += sld[t + s]; }
        __syncthreads();
    }
    if (t == 0) {
        const double E1 = se1[0];
        const double E2 = (double)NPTS * log(2.0 * M_PI) - 0.5 * sld[0];
        const double E  = E1 + (2.0 / 7.0) * E2;
        out[0] = (float)(0.3 * E);
        out[1] = (float)E1;
        out[2] = (float)E2;
    }
}

extern "C" void kernel_launch(void* const* d_in, const int* in_sizes, int n_in,
                              void* d_out, int out_size) {
    const float* Fa = (const float*)d_in[0];
    const float* Fb = (const float*)d_in[1];
    const float* ma = (const float*)d_in[2];
    const float* mb = (const float*)d_in[3];
    const float* nz = (const float*)d_in[4];
    float* out = (float*)d_out;

    gn_main_kernel<<<NBLOCKS, 256>>>(Fa, Fb, ma, mb, nz);
    gn_finalize_kernel<<<1, 256>>>(out);
}